// round 4
// baseline (speedup 1.0000x reference)
#include <cuda_runtime.h>
#include <cstdint>

#define T_LEN   1024
#define N_ORD   64
#define M_ROWS  512            // 4*2*64
#define KCHUNK  32
#define KSPLIT  (T_LEN / KCHUNK)   // 32
#define MTILE   32
#define MTILES  (M_ROWS / MTILE)   // 16
#define USTR    33             // padded uS row stride (conflict-free scalar A reads)

// Split-K partial buffer: 32 * 512 * 64 floats = 4 MB (static device scratch — allowed)
__device__ float g_partial[KSPLIT * M_ROWS * N_ORD];

// Packed f32x2 FMA (sm_103a): d.lo += a.lo*b.lo; d.hi += a.hi*b.hi
#define FFMA2(d, a, b) \
    asm("fma.rn.f32x2 %0, %1, %2, %0;" : "+l"(d) : "l"(a), "l"(b))
#define PACK2(d, f) \
    asm("mov.b64 %0, {%1, %1};" : "=l"(d) : "f"(f))

// out[r, n] = sum_t u[r, t] * K[n, T-1-t]
// Split-K GEMM. grid = (MTILES, KSPLIT) = (16, 32) = 512 blocks, 128 threads.
// Block tile: 32 rows x 64 cols over a K-chunk of 32.
// Per-thread microtile: 2 rows x 8 cols, accumulated as 8 f32x2 pairs.
__global__ __launch_bounds__(128) void hippo_gemm(
    const float* __restrict__ u,
    const float* __restrict__ Km)
{
    __shared__ float uS[MTILE * USTR];      // uS[r][kk] = u[m0+r][k0+kk]
    __shared__ float kS[KCHUNK * N_ORD];    // kS[kk][n] = Km[n][T-1-k0-kk] (transposed!)

    const int m0  = blockIdx.x * MTILE;
    const int k0  = blockIdx.y * KCHUNK;
    const int tid = threadIdx.x;

    // ---- load u tile (32 rows x 32 t), float4 coalesced ----
    #pragma unroll
    for (int i = tid; i < MTILE * KCHUNK / 4; i += 128) {   // 256 float4, 2 iters
        int r  = i >> 3;             // 0..31
        int c4 = (i & 7) << 2;       // 0..28
        float4 v = *(const float4*)(u + (m0 + r) * T_LEN + k0 + c4);
        uS[r * USTR + c4 + 0] = v.x;
        uS[r * USTR + c4 + 1] = v.y;
        uS[r * USTR + c4 + 2] = v.z;
        uS[r * USTR + c4 + 3] = v.w;
    }
    // ---- load K tile, time-reversed + transposed during store ----
    // lane->n mapping gives 32 distinct banks per scalar STS (conflict-free).
    #pragma unroll
    for (int i = tid; i < N_ORD * KCHUNK / 4; i += 128) {   // 512 float4, 4 iters
        int n  = i & 63;
        int c4 = (i >> 6) << 2;      // 0..28
        // components: g.x = Km[n][T-4-k0-c4] -> kk=c4+3 ... g.w -> kk=c4
        float4 g = *(const float4*)(Km + n * T_LEN + (T_LEN - 4 - k0 - c4));
        kS[(c4 + 0) * N_ORD + n] = g.w;
        kS[(c4 + 1) * N_ORD + n] = g.z;
        kS[(c4 + 2) * N_ORD + n] = g.y;
        kS[(c4 + 3) * N_ORD + n] = g.x;
    }
    __syncthreads();

    const int tx = tid & 7;     // col group: n0 = tx*8
    const int ty = tid >> 3;    // row group: rows ty*2, ty*2+1
    const int n0 = tx * 8;
    const int r0 = ty * 2;

    unsigned long long acc[2][4] = {};   // 2 rows x 4 f32x2 pairs (8 cols)

    #pragma unroll
    for (int kk = 0; kk < KCHUNK; kk++) {
        float a0 = uS[(r0 + 0) * USTR + kk];
        float a1 = uS[(r0 + 1) * USTR + kk];
        unsigned long long a0p, a1p;
        PACK2(a0p, a0);
        PACK2(a1p, a1);
        // 8 contiguous B values at fixed kk -> two 16B loads, conflict-free
        const ulonglong2 b01 = *(const ulonglong2*)&kS[kk * N_ORD + n0];
        const ulonglong2 b23 = *(const ulonglong2*)&kS[kk * N_ORD + n0 + 4];
        FFMA2(acc[0][0], a0p, b01.x);
        FFMA2(acc[0][1], a0p, b01.y);
        FFMA2(acc[0][2], a0p, b23.x);
        FFMA2(acc[0][3], a0p, b23.y);
        FFMA2(acc[1][0], a1p, b01.x);
        FFMA2(acc[1][1], a1p, b01.y);
        FFMA2(acc[1][2], a1p, b23.x);
        FFMA2(acc[1][3], a1p, b23.y);
    }

    // ---- write split-K partials (coalesced STG.128, no atomics) ----
    size_t base = ((size_t)blockIdx.y * M_ROWS + m0) * N_ORD;
    #pragma unroll
    for (int i = 0; i < 2; i++) {
        ulonglong2* p = (ulonglong2*)&g_partial[base + (size_t)(r0 + i) * N_ORD + n0];
        p[0] = make_ulonglong2(acc[i][0], acc[i][1]);
        p[1] = make_ulonglong2(acc[i][2], acc[i][3]);
    }
}

// Reduce KSPLIT partials into the output. 8192 float4 outputs.
__global__ __launch_bounds__(128) void hippo_reduce(float* __restrict__ out)
{
    int i = blockIdx.x * blockDim.x + threadIdx.x;   // 0..8191
    const float4* p = (const float4*)g_partial;
    const int stride = M_ROWS * N_ORD / 4;           // 8192
    float4 s = p[i];
    #pragma unroll
    for (int kb = 1; kb < KSPLIT; kb++) {
        float4 v = p[kb * stride + i];
        s.x += v.x; s.y += v.y; s.z += v.z; s.w += v.w;
    }
    ((float4*)out)[i] = s;
}

extern "C" void kernel_launch(void* const* d_in, const int* in_sizes, int n_in,
                              void* d_out, int out_size)
{
    const float* u  = (const float*)d_in[0];   // (4,2,64,1024) = 512 x 1024
    const float* Km = (const float*)d_in[1];   // (64,1024)
    if (n_in >= 2 && in_sizes[0] == N_ORD * T_LEN && in_sizes[1] == M_ROWS * T_LEN) {
        u  = (const float*)d_in[1];
        Km = (const float*)d_in[0];
    }
    float* out = (float*)d_out;                // (4,2,64,64) = 32768 floats

    dim3 grid(MTILES, KSPLIT);                 // 16 x 32 = 512 blocks
    hippo_gemm<<<grid, 128>>>(u, Km);
    hippo_reduce<<<(M_ROWS * N_ORD / 4) / 128, 128>>>(out);   // 64 blocks
}

// round 8
// speedup vs baseline: 1.1400x; 1.1400x over previous
#include <cuda_runtime.h>
#include <cstdint>

#define T_LEN   1024
#define N_ORD   64
#define M_ROWS  512            // 4*2*64
#define KCHUNK  64
#define KSPLIT  (T_LEN / KCHUNK)   // 16
#define MTILE   32
#define MTILES  (M_ROWS / MTILE)   // 16
#define UPAD    65             // uD row stride in float2 units (conflict-free)

// Packed f32x2 FMA (sm_103a): d.lo += a.lo*b.lo; d.hi += a.hi*b.hi
#define FFMA2(d, a, b) \
    asm("fma.rn.f32x2 %0, %1, %2, %0;" : "+l"(d) : "l"(a), "l"(b))

// Vectorized no-return reduction: out[0..3] += {pair0, pair1} (sm_90+)
#define REDV4(ptr, p0, p1) \
    asm volatile("{\n\t" \
        ".reg .f32 ra, rb, rc, rd;\n\t" \
        "mov.b64 {ra, rb}, %1;\n\t" \
        "mov.b64 {rc, rd}, %2;\n\t" \
        "red.global.add.v4.f32 [%0], {ra, rb, rc, rd};\n\t" \
        "}" :: "l"(ptr), "l"(p0), "l"(p1) : "memory")

__global__ __launch_bounds__(128) void hippo_zero(float* __restrict__ out) {
    int i = blockIdx.x * blockDim.x + threadIdx.x;
    ((float4*)out)[i] = make_float4(0.f, 0.f, 0.f, 0.f);
}

// out[r, n] += sum over this block's K-chunk of u[r, t] * K[n, T-1-t]
// grid = (MTILES, KSPLIT) = (16, 16) = 256 blocks, 128 threads.
// Block tile: 32 rows x 64 cols x 64 k. Per-thread: 2 rows x 8 cols (f32x2 pairs).
__global__ __launch_bounds__(128) void hippo_gemm(
    const float* __restrict__ u,
    const float* __restrict__ Km,
    float* __restrict__ out)
{
    __shared__ float2 uD[MTILE * UPAD];     // uD[r][kk] = (u, u) duplicated
    __shared__ float  kS[KCHUNK * N_ORD];   // kS[kk][n] = Km[n][T-1-k0-kk] (transposed)

    const int m0  = blockIdx.x * MTILE;
    const int k0  = blockIdx.y * KCHUNK;
    const int tid = threadIdx.x;

    // ---- load u tile (32 rows x 64 t): front-batch all 4 LDG.128, then STS ----
    {
        float4 v[4];
        int r[4], c4[4];
        #pragma unroll
        for (int it = 0; it < 4; it++) {                 // 512 float4 total
            int i  = tid + it * 128;
            r[it]  = i >> 4;             // 0..31
            c4[it] = (i & 15) << 2;      // 0..60
            v[it]  = *(const float4*)(u + (m0 + r[it]) * T_LEN + k0 + c4[it]);
        }
        #pragma unroll
        for (int it = 0; it < 4; it++) {
            uD[r[it] * UPAD + c4[it] + 0] = make_float2(v[it].x, v[it].x);
            uD[r[it] * UPAD + c4[it] + 1] = make_float2(v[it].y, v[it].y);
            uD[r[it] * UPAD + c4[it] + 2] = make_float2(v[it].z, v[it].z);
            uD[r[it] * UPAD + c4[it] + 3] = make_float2(v[it].w, v[it].w);
        }
    }
    // ---- load K tile (64 n x 64 t), time-reversed + transposed, batched x2 ----
    #pragma unroll
    for (int ot = 0; ot < 4; ot++) {                     // 1024 float4 total
        float4 g[2];
        int n[2], c4[2];
        #pragma unroll
        for (int j = 0; j < 2; j++) {
            int i  = tid + (ot * 2 + j) * 128;
            n[j]   = i & 63;
            c4[j]  = (i >> 6) << 2;      // 0..60
            g[j]   = *(const float4*)(Km + n[j] * T_LEN + (T_LEN - 4 - k0 - c4[j]));
        }
        #pragma unroll
        for (int j = 0; j < 2; j++) {
            kS[(c4[j] + 0) * N_ORD + n[j]] = g[j].w;
            kS[(c4[j] + 1) * N_ORD + n[j]] = g[j].z;
            kS[(c4[j] + 2) * N_ORD + n[j]] = g[j].y;
            kS[(c4[j] + 3) * N_ORD + n[j]] = g[j].x;
        }
    }
    __syncthreads();

    const int tx = tid & 7;     // col group: n0 = tx*8
    const int ty = tid >> 3;    // row group: rows ty*2, ty*2+1
    const int n0 = tx * 8;
    const int r0 = ty * 2;

    unsigned long long acc[2][4] = {};   // 2 rows x 4 f32x2 pairs (8 cols)

    #pragma unroll 16
    for (int kk = 0; kk < KCHUNK; kk++) {
        unsigned long long a0 = *(const unsigned long long*)&uD[(r0 + 0) * UPAD + kk];
        unsigned long long a1 = *(const unsigned long long*)&uD[(r0 + 1) * UPAD + kk];
        const ulonglong2 b01 = *(const ulonglong2*)&kS[kk * N_ORD + n0];
        const ulonglong2 b23 = *(const ulonglong2*)&kS[kk * N_ORD + n0 + 4];
        FFMA2(acc[0][0], a0, b01.x);
        FFMA2(acc[0][1], a0, b01.y);
        FFMA2(acc[0][2], a0, b23.x);
        FFMA2(acc[0][3], a0, b23.y);
        FFMA2(acc[1][0], a1, b01.x);
        FFMA2(acc[1][1], a1, b01.y);
        FFMA2(acc[1][2], a1, b23.x);
        FFMA2(acc[1][3], a1, b23.y);
    }

    // ---- vectorized reduction into output (no partial buffer, no reduce pass) ----
    #pragma unroll
    for (int i = 0; i < 2; i++) {
        float* p = out + (size_t)(m0 + r0 + i) * N_ORD + n0;
        REDV4(p,     acc[i][0], acc[i][1]);
        REDV4(p + 4, acc[i][2], acc[i][3]);
    }
}

extern "C" void kernel_launch(void* const* d_in, const int* in_sizes, int n_in,
                              void* d_out, int out_size)
{
    const float* u  = (const float*)d_in[0];   // (4,2,64,1024) = 512 x 1024
    const float* Km = (const float*)d_in[1];   // (64,1024)
    if (n_in >= 2 && in_sizes[0] == N_ORD * T_LEN && in_sizes[1] == M_ROWS * T_LEN) {
        u  = (const float*)d_in[1];
        Km = (const float*)d_in[0];
    }
    float* out = (float*)d_out;                // (4,2,64,64) = 32768 floats

    hippo_zero<<<(M_ROWS * N_ORD / 4) / 128, 128>>>(out);   // 64 blocks
    dim3 grid(MTILES, KSPLIT);                              // 16 x 16 = 256 blocks
    hippo_gemm<<<grid, 128>>>(u, Km, out);
}

// round 9
// speedup vs baseline: 1.3528x; 1.1866x over previous
#include <cuda_runtime.h>
#include <cstdint>

#define T_LEN   1024
#define N_ORD   64
#define M_ROWS  512                // 4*2*64
#define KCHUNK  32
#define KSPLIT  (T_LEN / KCHUNK)   // 32
#define MTILE   32
#define MTILES  (M_ROWS / MTILE)   // 16
#define USTR    34                 // uT row stride in floats (8B-aligned pairs, conflict-free)

// Packed f32x2 FMA (sm_103a): d.lo += a.lo*b.lo; d.hi += a.hi*b.hi
#define FFMA2(d, a, b) \
    asm("fma.rn.f32x2 %0, %1, %2, %0;" : "+l"(d) : "l"(a), "l"(b))
#define PACK2(d, f) \
    asm("mov.b64 %0, {%1, %1};" : "=l"(d) : "f"(f))

// Vectorized no-return reduction: out[0..3] += {pair0, pair1} (sm_90+)
#define REDV4(ptr, p0, p1) \
    asm volatile("{\n\t" \
        ".reg .f32 ra, rb, rc, rd;\n\t" \
        "mov.b64 {ra, rb}, %1;\n\t" \
        "mov.b64 {rc, rd}, %2;\n\t" \
        "red.global.add.v4.f32 [%0], {ra, rb, rc, rd};\n\t" \
        "}" :: "l"(ptr), "l"(p0), "l"(p1) : "memory")

__global__ __launch_bounds__(128) void hippo_zero(float* __restrict__ out) {
    int i = blockIdx.x * blockDim.x + threadIdx.x;
    ((float4*)out)[i] = make_float4(0.f, 0.f, 0.f, 0.f);
}

// out[r, n] += sum over this block's K-chunk of u[r, t] * K[n, T-1-t]
// grid = (MTILES, KSPLIT) = (16, 32) = 512 blocks, 128 threads.
// Per-thread microtile: 2 rows x 8 cols, cols = {tx*4..+3} u {32+tx*4..+3}.
__global__ __launch_bounds__(128, 8) void hippo_gemm(
    const float* __restrict__ u,
    const float* __restrict__ Km,
    float* __restrict__ out)
{
    __shared__ float uT[KCHUNK * USTR];     // uT[kk][r] = u[m0+r][k0+kk] (transposed)
    __shared__ float kS[KCHUNK * N_ORD];    // kS[kk][n] = Km[n][T-1-k0-kk]

    const int m0  = blockIdx.x * MTILE;
    const int k0  = blockIdx.y * KCHUNK;
    const int tid = threadIdx.x;

    // ---- front-batch all global loads (2 u + 4 K float4 per thread) ----
    float4 uv[2];
    int ur[2], uc[2];
    #pragma unroll
    for (int it = 0; it < 2; it++) {                 // 256 float4 (32r x 32t)
        int i  = tid + it * 128;
        ur[it] = i >> 3;             // 0..31
        uc[it] = (i & 7) << 2;       // 0..28
        uv[it] = *(const float4*)(u + (m0 + ur[it]) * T_LEN + k0 + uc[it]);
    }
    float4 kg[4];
    int kn[4], kc[4];
    #pragma unroll
    for (int it = 0; it < 4; it++) {                 // 512 float4 (64n x 32t)
        int i  = tid + it * 128;
        kn[it] = i & 63;
        kc[it] = (i >> 6) << 2;      // 0..28
        kg[it] = *(const float4*)(Km + kn[it] * T_LEN + (T_LEN - 4 - k0 - kc[it]));
    }
    // ---- stores: u transposed, K transposed + time-reversed ----
    #pragma unroll
    for (int it = 0; it < 2; it++) {
        uT[(uc[it] + 0) * USTR + ur[it]] = uv[it].x;
        uT[(uc[it] + 1) * USTR + ur[it]] = uv[it].y;
        uT[(uc[it] + 2) * USTR + ur[it]] = uv[it].z;
        uT[(uc[it] + 3) * USTR + ur[it]] = uv[it].w;
    }
    #pragma unroll
    for (int it = 0; it < 4; it++) {
        kS[(kc[it] + 0) * N_ORD + kn[it]] = kg[it].w;
        kS[(kc[it] + 1) * N_ORD + kn[it]] = kg[it].z;
        kS[(kc[it] + 2) * N_ORD + kn[it]] = kg[it].y;
        kS[(kc[it] + 3) * N_ORD + kn[it]] = kg[it].x;
    }
    __syncthreads();

    const int tx = tid & 7;     // col group: n-cols tx*4..+3 and 32+tx*4..+3
    const int ty = tid >> 3;    // row group: rows ty*2, ty*2+1
    const int n0 = tx * 4;
    const int r0 = ty * 2;

    unsigned long long acc[2][4] = {};   // [row][pair]: n = n0,n0+1 | n0+2,n0+3 | +32...

    // prefetch k=0
    float2     a  = *(const float2*)&uT[0 * USTR + r0];             // LDS.64
    ulonglong2 bl = *(const ulonglong2*)&kS[0 * N_ORD + n0];        // LDS.128
    ulonglong2 bh = *(const ulonglong2*)&kS[0 * N_ORD + 32 + n0];   // LDS.128

    #pragma unroll
    for (int kk = 0; kk < KCHUNK; kk++) {
        float2 an; ulonglong2 bln, bhn;
        if (kk + 1 < KCHUNK) {
            an  = *(const float2*)&uT[(kk + 1) * USTR + r0];
            bln = *(const ulonglong2*)&kS[(kk + 1) * N_ORD + n0];
            bhn = *(const ulonglong2*)&kS[(kk + 1) * N_ORD + 32 + n0];
        }
        unsigned long long a0p, a1p;
        PACK2(a0p, a.x);
        PACK2(a1p, a.y);
        FFMA2(acc[0][0], a0p, bl.x);
        FFMA2(acc[0][1], a0p, bl.y);
        FFMA2(acc[0][2], a0p, bh.x);
        FFMA2(acc[0][3], a0p, bh.y);
        FFMA2(acc[1][0], a1p, bl.x);
        FFMA2(acc[1][1], a1p, bl.y);
        FFMA2(acc[1][2], a1p, bh.x);
        FFMA2(acc[1][3], a1p, bh.y);
        a = an; bl = bln; bh = bhn;
    }

    // ---- vectorized reduction into output ----
    #pragma unroll
    for (int i = 0; i < 2; i++) {
        float* p = out + (size_t)(m0 + r0 + i) * N_ORD + n0;
        REDV4(p,      acc[i][0], acc[i][1]);
        REDV4(p + 32, acc[i][2], acc[i][3]);
    }
}

extern "C" void kernel_launch(void* const* d_in, const int* in_sizes, int n_in,
                              void* d_out, int out_size)
{
    const float* u  = (const float*)d_in[0];   // (4,2,64,1024) = 512 x 1024
    const float* Km = (const float*)d_in[1];   // (64,1024)
    if (n_in >= 2 && in_sizes[0] == N_ORD * T_LEN && in_sizes[1] == M_ROWS * T_LEN) {
        u  = (const float*)d_in[1];
        Km = (const float*)d_in[0];
    }
    float* out = (float*)d_out;                // (4,2,64,64) = 32768 floats

    hippo_zero<<<(M_ROWS * N_ORD / 4) / 128, 128>>>(out);   // 64 blocks
    dim3 grid(MTILES, KSPLIT);                              // 16 x 32 = 512 blocks
    hippo_gemm<<<grid, 128>>>(u, Km, out);
}

// round 13
// speedup vs baseline: 1.4410x; 1.0652x over previous
#include <cuda_runtime.h>
#include <cstdint>

#define T_LEN   1024
#define N_ORD   64
#define M_ROWS  512                // 4*2*64
#define KCHUNK  16
#define KSPLIT  (T_LEN / KCHUNK)   // 64
#define MTILE   32
#define MTILES  (M_ROWS / MTILE)   // 16
#define USTR    34                 // uT row stride in floats (8B-aligned pairs, conflict-free)

// Packed f32x2 FMA (sm_103a): d.lo += a.lo*b.lo; d.hi += a.hi*b.hi
#define FFMA2(d, a, b) \
    asm("fma.rn.f32x2 %0, %1, %2, %0;" : "+l"(d) : "l"(a), "l"(b))
#define PACK2(d, f) \
    asm("mov.b64 %0, {%1, %1};" : "=l"(d) : "f"(f))

// Vectorized no-return reduction: out[0..3] += {pair0, pair1} (sm_90+)
#define REDV4(ptr, p0, p1) \
    asm volatile("{\n\t" \
        ".reg .f32 ra, rb, rc, rd;\n\t" \
        "mov.b64 {ra, rb}, %1;\n\t" \
        "mov.b64 {rc, rd}, %2;\n\t" \
        "red.global.add.v4.f32 [%0], {ra, rb, rc, rd};\n\t" \
        "}" :: "l"(ptr), "l"(p0), "l"(p1) : "memory")

__global__ __launch_bounds__(128) void hippo_zero(float* __restrict__ out) {
    int i = blockIdx.x * blockDim.x + threadIdx.x;
    ((float4*)out)[i] = make_float4(0.f, 0.f, 0.f, 0.f);
}

// out[r, n] += sum over this block's K-chunk of u[r, t] * K[n, T-1-t]
// grid = (MTILES, KSPLIT) = (16, 64) = 1024 blocks, 128 threads.
// Block tile: 32 rows x 64 cols x 16 k. Per-thread: 2 rows x 8 cols
// (cols {tx*4..+3} u {32+tx*4..+3}), accumulated as f32x2 pairs.
__global__ __launch_bounds__(128, 8) void hippo_gemm(
    const float* __restrict__ u,
    const float* __restrict__ Km,
    float* __restrict__ out)
{
    __shared__ float uT[KCHUNK * USTR];     // uT[kk][r] = u[m0+r][k0+kk] (transposed)
    __shared__ float kS[KCHUNK * N_ORD];    // kS[kk][n] = Km[n][T-1-k0-kk]

    const int m0  = blockIdx.x * MTILE;
    const int k0  = blockIdx.y * KCHUNK;
    const int tid = threadIdx.x;

    // ---- front-batch global loads: 1 u-float4 + 2 K-float4 per thread ----
    const int ur = tid >> 2;              // 0..31
    const int uc = (tid & 3) << 2;        // 0,4,8,12
    float4 uv = *(const float4*)(u + (m0 + ur) * T_LEN + k0 + uc);

    float4 kg[2];
    int kn[2], kc[2];
    #pragma unroll
    for (int it = 0; it < 2; it++) {      // 256 float4 (64n x 16t)
        int i  = tid + it * 128;
        kn[it] = i & 63;
        kc[it] = (i >> 6) << 2;           // 0,4,8,12
        kg[it] = *(const float4*)(Km + kn[it] * T_LEN + (T_LEN - 4 - k0 - kc[it]));
    }

    // ---- stores: u transposed, K transposed + time-reversed ----
    uT[(uc + 0) * USTR + ur] = uv.x;
    uT[(uc + 1) * USTR + ur] = uv.y;
    uT[(uc + 2) * USTR + ur] = uv.z;
    uT[(uc + 3) * USTR + ur] = uv.w;
    #pragma unroll
    for (int it = 0; it < 2; it++) {
        kS[(kc[it] + 0) * N_ORD + kn[it]] = kg[it].w;
        kS[(kc[it] + 1) * N_ORD + kn[it]] = kg[it].z;
        kS[(kc[it] + 2) * N_ORD + kn[it]] = kg[it].y;
        kS[(kc[it] + 3) * N_ORD + kn[it]] = kg[it].x;
    }
    __syncthreads();

    const int tx = tid & 7;     // col group: n-cols tx*4..+3 and 32+tx*4..+3
    const int ty = tid >> 3;    // row group: rows ty*2, ty*2+1
    const int n0 = tx * 4;
    const int r0 = ty * 2;

    unsigned long long acc[2][4] = {};   // [row][pair]

    #pragma unroll
    for (int kk = 0; kk < KCHUNK; kk++) {
        float2     a  = *(const float2*)&uT[kk * USTR + r0];           // LDS.64
        ulonglong2 bl = *(const ulonglong2*)&kS[kk * N_ORD + n0];      // LDS.128
        ulonglong2 bh = *(const ulonglong2*)&kS[kk * N_ORD + 32 + n0]; // LDS.128
        unsigned long long a0p, a1p;
        PACK2(a0p, a.x);
        PACK2(a1p, a.y);
        FFMA2(acc[0][0], a0p, bl.x);
        FFMA2(acc[0][1], a0p, bl.y);
        FFMA2(acc[0][2], a0p, bh.x);
        FFMA2(acc[0][3], a0p, bh.y);
        FFMA2(acc[1][0], a1p, bl.x);
        FFMA2(acc[1][1], a1p, bl.y);
        FFMA2(acc[1][2], a1p, bh.x);
        FFMA2(acc[1][3], a1p, bh.y);
    }

    // ---- vectorized reduction into output ----
    #pragma unroll
    for (int i = 0; i < 2; i++) {
        float* p = out + (size_t)(m0 + r0 + i) * N_ORD + n0;
        REDV4(p,      acc[i][0], acc[i][1]);
        REDV4(p + 32, acc[i][2], acc[i][3]);
    }
}

extern "C" void kernel_launch(void* const* d_in, const int* in_sizes, int n_in,
                              void* d_out, int out_size)
{
    const float* u  = (const float*)d_in[0];   // (4,2,64,1024) = 512 x 1024
    const float* Km = (const float*)d_in[1];   // (64,1024)
    if (n_in >= 2 && in_sizes[0] == N_ORD * T_LEN && in_sizes[1] == M_ROWS * T_LEN) {
        u  = (const float*)d_in[1];
        Km = (const float*)d_in[0];
    }
    float* out = (float*)d_out;                // (4,2,64,64) = 32768 floats

    hippo_zero<<<(M_ROWS * N_ORD / 4) / 128, 128>>>(out);   // 64 blocks
    dim3 grid(MTILES, KSPLIT);                              // 16 x 64 = 1024 blocks
    hippo_gemm<<<grid, 128>>>(u, Km, out);
}